// round 17
// baseline (speedup 1.0000x reference)
#include <cuda_runtime.h>
#include <stdint.h>

// Canny magnitude, fused gray+hblur phase (no gray smem buffer), float4,
// smem-aliased (21.4KB), 512 threads on 64x32 tile, 3 barriers.
// Input (16,3,512,512) f32, output (16,1,512,512) f32.

#define H_IMG 512
#define W_IMG 512
#define PLANE (H_IMG * W_IMG)
#define TX 64
#define TY 32
#define NT 512

#define HH 40   // htmp rows (vertical halo 4)
#define HW 68   // htmp stride (horizontal halo 2) = 17 float4
#define BH 36   // blur rows
#define BW 68   // blur stride (valid cols 0..67)
#define MH 34
#define MW 68   // mag stride (valid cols 0..65; 66,67 pad = 0)

#define MAG_F (MH * MW)          // 2312 floats
#define SA_F (MAG_F + 578)       // 2890: htmp (2720) then mag+dir words
#define SB_F (BH * BW)           // 2448: blur

__device__ __forceinline__ int reflect_idx(int i, int n) {
    if (i < 0) i = -i;
    if (i >= n) i = 2 * n - 2 - i;
    return i;
}

// NMS linear offset in mag tile (stride 68), arithmetic (no LUT).
__device__ __forceinline__ int nms_dir(float gx, float gy) {
    float ax = fabsf(gx), ay = fabsf(gy);
    int sx = 1 | (__float_as_int(gx) >> 31);
    int sy = 1 | (__float_as_int(gy) >> 31);
    int dy = (ay > 0.4142135623730950f * ax) ? -sy : 0;
    int dx = (ay > 2.4142135623730950f * ax) ? 0 : sx;
    return dx + 68 * dy;
}

#define GQ0 0.054488684548643f
#define GQ1 0.244201342003233f
#define GQ2 0.402619946896247f

__device__ __forceinline__ float gray_of(float r, float g, float b) {
    return fmaf(0.1495f, r, fmaf(0.2935f, g, fmaf(0.057f, b, 0.5f)));
}

__global__ void __launch_bounds__(NT, 4)
canny_fused_kernel(const float* __restrict__ in, float* __restrict__ out) {
    __shared__ __align__(16) float sA[SA_F];   // htmp -> mag + dir words
    __shared__ __align__(16) float sB[SB_F];   // blur

    float*    sH    = sA;
    float*    sBlur = sB;
    float*    sMag  = sA;
    uint32_t* sDw   = (uint32_t*)(sA + MAG_F);
    int8_t*   sDb   = (int8_t*)(sA + MAG_F);

    const int tid = threadIdx.x;
    const int x0  = blockIdx.x * TX;
    const int y0  = blockIdx.y * TY;
    const int b   = blockIdx.z;

    const float* base = in + (size_t)b * 3 * PLANE;

    const bool interior = (x0 >= 4) && (x0 + TX + 4 <= W_IMG) &&
                          (y0 >= 4) && (y0 + TY + 4 <= H_IMG);

    // ---- Phase F1: fused grayscale + horizontal blur -> sH (HH x 17 = 680) ----
    if (interior) {
        const float* p = base + (y0 - 4) * W_IMG + (x0 - 4);  // 16B aligned
        #pragma unroll
        for (int it = 0; it < 2; it++) {
            int i = tid + it * NT;
            if (i < HH * 17) {
                int r = i / 17, c4 = (i - r * 17) * 4;
                const float* q = p + r * W_IMG + c4;
                float4 Ra = *(const float4*)q;
                float4 Rb = *(const float4*)(q + 4);
                float4 Ga = *(const float4*)(q + PLANE);
                float4 Gb = *(const float4*)(q + PLANE + 4);
                float4 Ba = *(const float4*)(q + 2 * PLANE);
                float4 Bb = *(const float4*)(q + 2 * PLANE + 4);
                float g0 = gray_of(Ra.x, Ga.x, Ba.x);
                float g1 = gray_of(Ra.y, Ga.y, Ba.y);
                float g2 = gray_of(Ra.z, Ga.z, Ba.z);
                float g3 = gray_of(Ra.w, Ga.w, Ba.w);
                float g4 = gray_of(Rb.x, Gb.x, Bb.x);
                float g5 = gray_of(Rb.y, Gb.y, Bb.y);
                float g6 = gray_of(Rb.z, Gb.z, Bb.z);
                float g7 = gray_of(Rb.w, Gb.w, Bb.w);
                float4 o;
                o.x = GQ0 * (g0 + g4) + GQ1 * (g1 + g3) + GQ2 * g2;
                o.y = GQ0 * (g1 + g5) + GQ1 * (g2 + g4) + GQ2 * g3;
                o.z = GQ0 * (g2 + g6) + GQ1 * (g3 + g5) + GQ2 * g4;
                o.w = GQ0 * (g3 + g7) + GQ1 * (g4 + g6) + GQ2 * g5;
                *(float4*)(sH + r * HW + c4) = o;
            }
        }
    } else {
        #pragma unroll 1
        for (int i = tid; i < HH * 17; i += NT) {
            int r = i / 17, c4 = (i - r * 17) * 4;
            int yy = reflect_idx(y0 - 4 + r, H_IMG) * W_IMG;
            // gray cols needed: image x0-4+c4 .. x0-4+c4+7
            float g[8];
            #pragma unroll
            for (int j = 0; j < 8; j++) {
                int off = yy + reflect_idx(x0 - 4 + c4 + j, W_IMG);
                g[j] = gray_of(base[off], base[off + PLANE], base[off + 2 * PLANE]);
            }
            float4 o;
            o.x = GQ0 * (g[0] + g[4]) + GQ1 * (g[1] + g[3]) + GQ2 * g[2];
            o.y = GQ0 * (g[1] + g[5]) + GQ1 * (g[2] + g[4]) + GQ2 * g[3];
            o.z = GQ0 * (g[2] + g[6]) + GQ1 * (g[3] + g[5]) + GQ2 * g[4];
            o.w = GQ0 * (g[3] + g[7]) + GQ1 * (g[4] + g[6]) + GQ2 * g[5];
            *(float4*)(sH + r * HW + c4) = o;
        }
    }
    __syncthreads();

    // ---- Phase 3: vertical blur sH -> sB(blur), 612 items ----
    #pragma unroll
    for (int it = 0; it < 2; it++) {
        int i = tid + it * NT;
        if (i < BH * 17) {
            int r = i / 17, c4 = (i - r * 17) * 4;
            const float* h = sH + r * HW + c4;
            float4 v0 = *(const float4*)h;
            float4 v1 = *(const float4*)(h + HW);
            float4 v2 = *(const float4*)(h + 2 * HW);
            float4 v3 = *(const float4*)(h + 3 * HW);
            float4 v4 = *(const float4*)(h + 4 * HW);
            float4 o;
            o.x = GQ0 * (v0.x + v4.x) + GQ1 * (v1.x + v3.x) + GQ2 * v2.x;
            o.y = GQ0 * (v0.y + v4.y) + GQ1 * (v1.y + v3.y) + GQ2 * v2.y;
            o.z = GQ0 * (v0.z + v4.z) + GQ1 * (v1.z + v3.z) + GQ2 * v2.z;
            o.w = GQ0 * (v0.w + v4.w) + GQ1 * (v1.w + v3.w) + GQ2 * v2.w;
            *(float4*)(sBlur + r * BW + c4) = o;
        }
    }
    __syncthreads();

    // ---- Phase 4: sobel + dir, sB(blur) -> sA(mag + packed dirs), 578 items ----
    // NOTE: overwrites sH region — all htmp consumers finished at the barrier.
    if (interior) {
        #pragma unroll
        for (int it = 0; it < 2; it++) {
            int i = tid + it * NT;
            if (i < MH * 17) {
                int r = i / 17, c0 = (i - r * 17) * 4;
                const float* bp = sBlur + r * BW + c0;
                float t0[8], t1[8], t2[8];
                *(float4*)t0       = *(const float4*)bp;
                *(float4*)(t0 + 4) = *(const float4*)(bp + 4);
                *(float4*)t1       = *(const float4*)(bp + BW);
                *(float4*)(t1 + 4) = *(const float4*)(bp + BW + 4);
                *(float4*)t2       = *(const float4*)(bp + 2 * BW);
                *(float4*)(t2 + 4) = *(const float4*)(bp + 2 * BW + 4);
                float A[8], C[8];
                #pragma unroll
                for (int j = 0; j < 8; j++) {
                    A[j] = t0[j] + 2.0f * t1[j] + t2[j];
                    C[j] = t2[j] - t0[j];
                }
                float m[4];
                uint32_t dpack = 0;
                #pragma unroll
                for (int j = 0; j < 4; j++) {
                    float gx = A[j + 2] - A[j];
                    float gy = C[j] + 2.0f * C[j + 1] + C[j + 2];
                    float mm = sqrtf(fmaf(gx, gx, fmaf(gy, gy, 1e-6f)));
                    int d = nms_dir(gx, gy);
                    if (c0 + j > 65) { mm = 0.0f; d = 1; }
                    m[j] = mm;
                    dpack |= ((uint32_t)(uint8_t)(int8_t)d) << (8 * j);
                }
                *(float4*)(sMag + r * MW + c0) = make_float4(m[0], m[1], m[2], m[3]);
                sDw[(r * MW + c0) >> 2] = dpack;
            }
        }
    } else {
        #pragma unroll 1
        for (int i = tid; i < MH * MW; i += NT) {
            int r = i / MW, c = i - r * MW;
            float mm = 0.0f;
            int8_t dch = 1;
            if (c <= 65) {
                int my = y0 - 1 + r;
                int mx = x0 - 1 + c;
                if (my >= 0 && my < H_IMG && mx >= 0 && mx < W_IMG) {
                    int iy0 = max(my - 1, 0)         - (y0 - 2);
                    int iy1 = r + 1;
                    int iy2 = min(my + 1, H_IMG - 1) - (y0 - 2);
                    int ix0 = max(mx - 1, 0)         - (x0 - 2);
                    int ix1 = c + 1;
                    int ix2 = min(mx + 1, W_IMG - 1) - (x0 - 2);
                    float b00 = sBlur[iy0*BW+ix0], b01 = sBlur[iy0*BW+ix1], b02 = sBlur[iy0*BW+ix2];
                    float b10 = sBlur[iy1*BW+ix0],                          b12 = sBlur[iy1*BW+ix2];
                    float b20 = sBlur[iy2*BW+ix0], b21 = sBlur[iy2*BW+ix1], b22 = sBlur[iy2*BW+ix2];
                    float gx = (b02 - b00) + 2.0f * (b12 - b10) + (b22 - b20);
                    float gy = (b20 - b00) + 2.0f * (b21 - b01) + (b22 - b02);
                    mm = sqrtf(fmaf(gx, gx, fmaf(gy, gy, 1e-6f)));
                    dch = (int8_t)nms_dir(gx, gy);
                }
            }
            sMag[i] = mm;
            sDb[i] = dch;
        }
    }
    __syncthreads();

    // ---- Phase 5: NMS + write, exactly 1 f4 item/thread ----
    float* obase = out + ((size_t)b * H_IMG + y0) * W_IMG + x0;
    {
        const int r  = tid >> 4;                  // 0..31
        const int c0 = (tid & 15) * 4;
        const int bse = (r + 1) * MW + c0;        // 16B aligned
        float4 m0 = *(const float4*)(sMag + bse);
        float4 m1 = *(const float4*)(sMag + bse + 4);
        uint32_t wlo = sDw[bse >> 2];
        uint32_t whi = sDw[(bse >> 2) + 1];
        uint32_t dv  = __funnelshift_r(wlo, whi, 8);  // dirs for cols c0+1..c0+4
        float ctr[4] = { m0.y, m0.z, m0.w, m1.x };
        float res[4];
        #pragma unroll
        for (int j = 0; j < 4; j++) {
            int d = (int)(int8_t)(dv >> (8 * j));
            int lin = bse + 1 + j;
            float mc = ctr[j];
            float sp = mc - sMag[lin + d];
            float sn = mc - sMag[lin - d];
            res[j] = (fminf(sp, sn) > 0.0f) ? mc : 0.0f;
        }
        *(float4*)(obase + r * W_IMG + c0) = make_float4(res[0], res[1], res[2], res[3]);
    }
}

extern "C" void kernel_launch(void* const* d_in, const int* in_sizes, int n_in,
                              void* d_out, int out_size) {
    const float* in = (const float*)d_in[0];
    float* out = (float*)d_out;
    dim3 grid(W_IMG / TX, H_IMG / TY, 16);   // (8, 16, 16)
    canny_fused_kernel<<<grid, NT>>>(in, out);
}